// round 13
// baseline (speedup 1.0000x reference)
#include <cuda_runtime.h>
#include <cuda_bf16.h>
#include <cstdint>

// MoE gate: logits = x[N,1024] @ W[4,1024]^T in exact fp32, softmax with
// FTZ-exp emulation, top-2 with lowest-index tie-break on flushed (zero)
// scores. Output (fp32): [ topk_idx (N*2) | topk_weight (N*2) | aux_loss(1) ]
// aux_loss == 0.01 analytically.
//
// R13: cp.async (LDGSTS) producer pipeline. Register-consumer variants are
// pinned at ~2GB/s/warp (R4-R12: ptxas batch->drain). Async copies need no
// registers: depth-3 ring of 16KB tiles keeps 32KB in flight per block,
// 3 blocks/SM = 96KB/SM >> 31KB Little's-law need for 8TB/s.
// Lane-level accumulation order is bit-identical to R5 (canary 1.032705e-06).

constexpr int H        = 1024;
constexpr int E        = 4;
constexpr int THREADS  = 256;
constexpr int GROUP_ROWS = 32;          // rows per block-group (8 warps x 4)
constexpr int SLOTS    = 3;             // pipeline depth
constexpr int TILE_F4  = GROUP_ROWS * 32;  // 1024 float4 = 16KB
constexpr int WS_F4    = E * (H / 4);      // 1024 float4 = 16KB
constexpr int SMEM_BYTES = (WS_F4 + SLOTS * TILE_F4) * 16;  // 64KB
constexpr int GRID     = 444;           // 3 blocks/SM * 148 SMs

#define EXP_FLUSH_T (-87.336544f)

__device__ __forceinline__ uint32_t s2u(const void* p) {
    return (uint32_t)__cvta_generic_to_shared(p);
}

__global__ __launch_bounds__(THREADS)
void moe_gate_kernel(const float* __restrict__ x,
                     const float* __restrict__ w,
                     float* __restrict__ out, int n, int ngroups)
{
    extern __shared__ float4 smem[];
    float4* ws = smem;                 // 16KB weights
    float4* xs = smem + WS_F4;         // 3 x 16KB x-tiles

    const int tid  = threadIdx.x;
    const int lane = tid & 31;
    const int wid  = tid >> 5;

    // Groups owned by this block: bid, bid+GRID, ...
    const int my_ngroups = (blockIdx.x < ngroups)
                         ? ((ngroups - 1 - blockIdx.x) / GRID + 1) : 0;
    const int total_tiles = my_ngroups * 8;

    // Producer: issue tile t (4 cp.async of 16B per thread) + always commit
    // a group (empty commits keep wait_group counting uniform at the tail).
    auto issue = [&](int t) {
        if (t < total_tiles) {
            const int g     = t >> 3;
            const int chunk = t & 7;
            const int row0  = (blockIdx.x + g * GRID) * GROUP_ROWS;
            float4* dst = xs + (t % SLOTS) * TILE_F4;
            #pragma unroll
            for (int m = 0; m < 4; m++) {
                const int idx = tid + m * THREADS;   // 0..1023
                int grow = row0 + (idx >> 5);
                if (grow >= n) grow = n - 1;         // clamp (store-gated)
                const float4* src =
                    reinterpret_cast<const float4*>(x + (size_t)grow * H)
                    + chunk * 32 + (idx & 31);
                asm volatile("cp.async.cg.shared.global [%0], [%1], 16;"
                             :: "r"(s2u(dst + idx)), "l"(src));
            }
        }
        asm volatile("cp.async.commit_group;");
    };

    // Prologue: start tiles 0,1 streaming, load weights meanwhile.
    issue(0);
    for (int i = tid; i < WS_F4; i += THREADS)
        ws[i] = reinterpret_cast<const float4*>(w)[i];
    issue(1);
    __syncthreads();

    if (blockIdx.x == 0 && tid == 0)
        out[4 * (size_t)n] = 0.01f;   // aux = 0.25*4*0.01 (analytic)

    float acc[4][E];
    #pragma unroll
    for (int r = 0; r < 4; r++)
        #pragma unroll
        for (int e = 0; e < E; e++) acc[r][e] = 0.0f;

    for (int ct = 0; ct < total_tiles; ct++) {
        asm volatile("cp.async.wait_group 1;" ::: "memory");
        __syncthreads();              // tile ct visible; slot (ct-1)%3 free
        issue(ct + 2);                // refill freed slot

        const int chunk = ct & 7;
        const int c = chunk * 32 + lane;
        const float4* xb = xs + (ct % SLOTS) * TILE_F4;

        float4 xv[4];
        #pragma unroll
        for (int r = 0; r < 4; r++)
            xv[r] = xb[(4 * wid + r) * 32 + lane];
        #pragma unroll
        for (int e = 0; e < E; e++) {
            const float4 wv = ws[e * (H / 4) + c];
            #pragma unroll
            for (int r = 0; r < 4; r++) {
                acc[r][e] += xv[r].x * wv.x;
                acc[r][e] += xv[r].y * wv.y;
                acc[r][e] += xv[r].z * wv.z;
                acc[r][e] += xv[r].w * wv.w;
            }
        }

        if (chunk == 7) {
            // ---- group epilogue (identical to R5, bit-exact) ----
            #pragma unroll
            for (int off = 16; off > 0; off >>= 1)
                #pragma unroll
                for (int r = 0; r < 4; r++)
                    #pragma unroll
                    for (int e = 0; e < E; e++)
                        acc[r][e] += __shfl_xor_sync(0xffffffffu, acc[r][e], off);

            const int row0 = (blockIdx.x + (ct >> 3) * GRID) * GROUP_ROWS
                           + 4 * wid;
            if (lane < 4 && (row0 + lane) < n) {
                float l[E];
                #pragma unroll
                for (int r = 0; r < 4; r++)
                    if (lane == r) {
                        #pragma unroll
                        for (int e = 0; e < E; e++) l[e] = acc[r][e];
                    }

                const float m = fmaxf(fmaxf(l[0], l[1]), fmaxf(l[2], l[3]));
                float p2[E];
                float s = 0.0f;
                #pragma unroll
                for (int e = 0; e < E; e++) {
                    const float aa = l[e] - m;
                    p2[e] = (aa <= EXP_FLUSH_T) ? 0.0f : expf(aa);
                    s += p2[e];
                }
                int i1 = 0; float b1 = p2[0];
                #pragma unroll
                for (int e = 1; e < E; e++)
                    if (p2[e] > b1) { b1 = p2[e]; i1 = e; }
                int i2 = -1; float b2 = -1.0f;
                #pragma unroll
                for (int e = 0; e < E; e++)
                    if (e != i1 && p2[e] > b2) { b2 = p2[e]; i2 = e; }

                const float inv = 1.0f / s;
                const int row = row0 + lane;
                reinterpret_cast<float2*>(out)[row] =
                    make_float2((float)i1, (float)i2);
                reinterpret_cast<float2*>(out + 2 * (size_t)n)[row] =
                    make_float2(b1 * inv, b2 * inv);
            }
            #pragma unroll
            for (int r = 0; r < 4; r++)
                #pragma unroll
                for (int e = 0; e < E; e++) acc[r][e] = 0.0f;
        }
    }
}

extern "C" void kernel_launch(void* const* d_in, const int* in_sizes, int n_in,
                              void* d_out, int out_size)
{
    const float* x = (const float*)d_in[0];
    const float* w = (const float*)d_in[1];
    float* out = (float*)d_out;

    const int h = in_sizes[1] / E;                    // 1024
    const int n = in_sizes[0] / h;                    // 32768 rows
    const int ngroups = (n + GROUP_ROWS - 1) / GROUP_ROWS;  // 1024
    (void)n_in; (void)out_size;

    static bool attr_done = false;
    if (!attr_done) {
        cudaFuncSetAttribute(moe_gate_kernel,
                             cudaFuncAttributeMaxDynamicSharedMemorySize,
                             SMEM_BYTES);
        attr_done = true;
    }

    moe_gate_kernel<<<GRID, THREADS, SMEM_BYTES>>>(x, w, out, n, ngroups);
}

// round 14
// speedup vs baseline: 1.0380x; 1.0380x over previous
#include <cuda_runtime.h>
#include <cuda_bf16.h>
#include <cstdint>

// MoE gate: logits = x[N,1024] @ W[4,1024]^T in exact fp32, softmax with
// FTZ-exp emulation, top-2 with lowest-index tie-break on flushed (zero)
// scores. Output (fp32): [ topk_idx (N*2) | topk_weight (N*2) | aux_loss(1) ]
// aux_loss == 0.01 analytically.
//
// R14: R13's cp.async pipeline with depth 6 (was 3). R13 exposed ~400-800cyc
// of DRAM latency per tile because only 2 tiles were in flight; 5-in-flight
// (wait_group 4) gives ~1200cyc of lead time > worst-case loaded latency.
// smem = 16KB weights + 6x16KB ring = 112KB -> 2 blocks/SM (16 warps/SM),
// 160KB in flight per SM. Consumer math is byte-identical to R5/R13
// (rel_err canary 1.032705e-06).

constexpr int H        = 1024;
constexpr int E        = 4;
constexpr int THREADS  = 256;
constexpr int GROUP_ROWS = 32;          // rows per block-group (8 warps x 4)
constexpr int SLOTS    = 6;             // pipeline depth
constexpr int AHEAD    = 4;             // wait_group operand: <=4 pending
constexpr int TILE_F4  = GROUP_ROWS * 32;  // 1024 float4 = 16KB
constexpr int WS_F4    = E * (H / 4);      // 1024 float4 = 16KB
constexpr int SMEM_BYTES = (WS_F4 + SLOTS * TILE_F4) * 16;  // 112KB
constexpr int GRID     = 296;           // 2 blocks/SM * 148 SMs

#define EXP_FLUSH_T (-87.336544f)

__device__ __forceinline__ uint32_t s2u(const void* p) {
    return (uint32_t)__cvta_generic_to_shared(p);
}

__global__ __launch_bounds__(THREADS)
void moe_gate_kernel(const float* __restrict__ x,
                     const float* __restrict__ w,
                     float* __restrict__ out, int n, int ngroups)
{
    extern __shared__ float4 smem[];
    float4* ws = smem;                 // 16KB weights
    float4* xs = smem + WS_F4;         // 6 x 16KB x-tiles

    const int tid  = threadIdx.x;
    const int lane = tid & 31;
    const int wid  = tid >> 5;

    // Groups owned by this block: bid, bid+GRID, ...
    const int my_ngroups = (blockIdx.x < ngroups)
                         ? ((ngroups - 1 - blockIdx.x) / GRID + 1) : 0;
    const int total_tiles = my_ngroups * 8;

    // Producer: issue tile t (4 cp.async of 16B per thread) + always commit
    // a group (empty commits keep wait_group counting uniform at the tail).
    auto issue = [&](int t) {
        if (t < total_tiles) {
            const int g     = t >> 3;
            const int chunk = t & 7;
            const int row0  = (blockIdx.x + g * GRID) * GROUP_ROWS;
            float4* dst = xs + (t % SLOTS) * TILE_F4;
            #pragma unroll
            for (int m = 0; m < 4; m++) {
                const int idx = tid + m * THREADS;   // 0..1023
                int grow = row0 + (idx >> 5);
                if (grow >= n) grow = n - 1;         // clamp (store-gated)
                const float4* src =
                    reinterpret_cast<const float4*>(x + (size_t)grow * H)
                    + chunk * 32 + (idx & 31);
                asm volatile("cp.async.cg.shared.global [%0], [%1], 16;"
                             :: "r"(s2u(dst + idx)), "l"(src));
            }
        }
        asm volatile("cp.async.commit_group;");
    };

    // Prologue: start tiles 0..4 streaming; load weights between them.
    issue(0);
    issue(1);
    for (int i = tid; i < WS_F4; i += THREADS)
        ws[i] = reinterpret_cast<const float4*>(w)[i];
    issue(2);
    issue(3);
    issue(4);
    __syncthreads();

    if (blockIdx.x == 0 && tid == 0)
        out[4 * (size_t)n] = 0.01f;   // aux = 0.25*4*0.01 (analytic)

    float acc[4][E];
    #pragma unroll
    for (int r = 0; r < 4; r++)
        #pragma unroll
        for (int e = 0; e < E; e++) acc[r][e] = 0.0f;

    for (int ct = 0; ct < total_tiles; ct++) {
        asm volatile("cp.async.wait_group %0;" :: "n"(AHEAD) : "memory");
        __syncthreads();              // tile ct visible; tile ct-1 consumed
        issue(ct + AHEAD + 1);        // refill: slot (ct-1)%SLOTS is free

        const int chunk = ct & 7;
        const int c = chunk * 32 + lane;
        const float4* xb = xs + (ct % SLOTS) * TILE_F4;

        float4 xv[4];
        #pragma unroll
        for (int r = 0; r < 4; r++)
            xv[r] = xb[(4 * wid + r) * 32 + lane];
        #pragma unroll
        for (int e = 0; e < E; e++) {
            const float4 wv = ws[e * (H / 4) + c];
            #pragma unroll
            for (int r = 0; r < 4; r++) {
                acc[r][e] += xv[r].x * wv.x;
                acc[r][e] += xv[r].y * wv.y;
                acc[r][e] += xv[r].z * wv.z;
                acc[r][e] += xv[r].w * wv.w;
            }
        }

        if (chunk == 7) {
            // ---- group epilogue (identical to R5/R13, bit-exact) ----
            #pragma unroll
            for (int off = 16; off > 0; off >>= 1)
                #pragma unroll
                for (int r = 0; r < 4; r++)
                    #pragma unroll
                    for (int e = 0; e < E; e++)
                        acc[r][e] += __shfl_xor_sync(0xffffffffu, acc[r][e], off);

            const int row0 = (blockIdx.x + (ct >> 3) * GRID) * GROUP_ROWS
                           + 4 * wid;
            if (lane < 4 && (row0 + lane) < n) {
                float l[E];
                #pragma unroll
                for (int r = 0; r < 4; r++)
                    if (lane == r) {
                        #pragma unroll
                        for (int e = 0; e < E; e++) l[e] = acc[r][e];
                    }

                const float m = fmaxf(fmaxf(l[0], l[1]), fmaxf(l[2], l[3]));
                float p2[E];
                float s = 0.0f;
                #pragma unroll
                for (int e = 0; e < E; e++) {
                    const float aa = l[e] - m;
                    p2[e] = (aa <= EXP_FLUSH_T) ? 0.0f : expf(aa);
                    s += p2[e];
                }
                int i1 = 0; float b1 = p2[0];
                #pragma unroll
                for (int e = 1; e < E; e++)
                    if (p2[e] > b1) { b1 = p2[e]; i1 = e; }
                int i2 = -1; float b2 = -1.0f;
                #pragma unroll
                for (int e = 0; e < E; e++)
                    if (e != i1 && p2[e] > b2) { b2 = p2[e]; i2 = e; }

                const float inv = 1.0f / s;
                const int row = row0 + lane;
                reinterpret_cast<float2*>(out)[row] =
                    make_float2((float)i1, (float)i2);
                reinterpret_cast<float2*>(out + 2 * (size_t)n)[row] =
                    make_float2(b1 * inv, b2 * inv);
            }
            #pragma unroll
            for (int r = 0; r < 4; r++)
                #pragma unroll
                for (int e = 0; e < E; e++) acc[r][e] = 0.0f;
        }
    }
}

extern "C" void kernel_launch(void* const* d_in, const int* in_sizes, int n_in,
                              void* d_out, int out_size)
{
    const float* x = (const float*)d_in[0];
    const float* w = (const float*)d_in[1];
    float* out = (float*)d_out;

    const int h = in_sizes[1] / E;                    // 1024
    const int n = in_sizes[0] / h;                    // 32768 rows
    const int ngroups = (n + GROUP_ROWS - 1) / GROUP_ROWS;  // 1024
    (void)n_in; (void)out_size;

    static bool attr_done = false;
    if (!attr_done) {
        cudaFuncSetAttribute(moe_gate_kernel,
                             cudaFuncAttributeMaxDynamicSharedMemorySize,
                             SMEM_BYTES);
        attr_done = true;
    }

    moe_gate_kernel<<<GRID, THREADS, SMEM_BYTES>>>(x, w, out, n, ngroups);
}

// round 15
// speedup vs baseline: 1.0471x; 1.0088x over previous
#include <cuda_runtime.h>
#include <cuda_bf16.h>
#include <cstdint>

// MoE gate: logits = x[N,1024] @ W[4,1024]^T in exact fp32, softmax with
// FTZ-exp emulation, top-2 with lowest-index tie-break on flushed (zero)
// scores. Output (fp32): [ topk_idx (N*2) | topk_weight (N*2) | aux_loss(1) ]
// aux_loss == 0.01 analytically.
//
// R15: contiguous-tile, warp-autonomous cp.async pipeline. All prior
// variants (R4-R14) read 128B pieces at 4KB stride and pinned at ~4.9TB/s
// with DRAM 38% idle -- page-locality theory. Here a tile = 2 FULL rows
// (8KB contiguous); each warp streams its own tiles through a private
// 3-slot ring with per-warp wait_group (no block barriers in the loop).
// Consumer math is bit-identical to R5 (rel_err canary 1.032705e-06).

constexpr int H        = 1024;
constexpr int E        = 4;
constexpr int THREADS  = 256;
constexpr int WARPS    = THREADS / 32;     // 8
constexpr int RPW      = 2;                // rows per warp-tile
constexpr int GROUP_ROWS = WARPS * RPW;    // 16 rows per block-iteration
constexpr int SLOTS    = 3;                // per-warp ring depth
constexpr int TILE_F4  = RPW * (H / 4);    // 512 float4 = 8KB
constexpr int WS_F4    = E * (H / 4);      // 1024 float4 = 16KB
constexpr int SMEM_BYTES = (WS_F4 + WARPS * SLOTS * TILE_F4) * 16;  // 208KB
constexpr int GRID     = 148;              // 1 block/SM, persistent

#define EXP_FLUSH_T (-87.336544f)

__device__ __forceinline__ uint32_t s2u(const void* p) {
    return (uint32_t)__cvta_generic_to_shared(p);
}

__global__ __launch_bounds__(THREADS)
void moe_gate_kernel(const float* __restrict__ x,
                     const float* __restrict__ w,
                     float* __restrict__ out, int n, int ngroups)
{
    extern __shared__ float4 smem[];
    float4* ws = smem;                       // 16KB weights
    float4* xs = smem + WS_F4;               // 8 x 3 x 8KB warp rings

    const int tid  = threadIdx.x;
    const int lane = tid & 31;
    const int wid  = tid >> 5;

    const int my_ngroups = (blockIdx.x < ngroups)
                         ? ((ngroups - 1 - blockIdx.x) / GRID + 1) : 0;

    float4* ring = xs + wid * SLOTS * TILE_F4;

    // Issue this warp's tile for group-index g: 2 contiguous rows (8KB).
    // Unconditional commit keeps wait_group counting uniform at the tail.
    auto issue = [&](int g) {
        if (g < my_ngroups) {
            int row0 = (blockIdx.x + g * GRID) * GROUP_ROWS + wid * RPW;
            if (row0 > n - RPW) row0 = n - RPW;     // safety clamp
            const float4* src =
                reinterpret_cast<const float4*>(x) + (size_t)row0 * (H / 4);
            float4* dst = ring + (g % SLOTS) * TILE_F4;
            #pragma unroll
            for (int i = 0; i < TILE_F4 / 32; i++) {   // 16 per lane
                const int idx = i * 32 + lane;          // 512B coalesced/instr
                asm volatile("cp.async.cg.shared.global [%0], [%1], 16;"
                             :: "r"(s2u(dst + idx)), "l"(src + idx));
            }
        }
        asm volatile("cp.async.commit_group;");
    };

    issue(0);
    issue(1);
    for (int i = tid; i < WS_F4; i += THREADS)
        ws[i] = reinterpret_cast<const float4*>(w)[i];
    __syncthreads();   // ws visible to all warps (only block sync)

    if (blockIdx.x == 0 && tid == 0)
        out[4 * (size_t)n] = 0.01f;    // aux = 0.25*4*0.01 (analytic)

    for (int g = 0; g < my_ngroups; g++) {
        issue(g + 2);                              // into freed slot (g-1)%3
        asm volatile("cp.async.wait_group 2;" ::: "memory");  // tile g ready

        const float4* xb = ring + (g % SLOTS) * TILE_F4;

        float acc[RPW][E];
        #pragma unroll
        for (int r = 0; r < RPW; r++)
            #pragma unroll
            for (int e = 0; e < E; e++) acc[r][e] = 0.0f;

        #pragma unroll
        for (int c = 0; c < 8; c++) {              // 8 chunks, same as R5
            const int ci = c * 32 + lane;
            float4 xv[RPW];
            xv[0] = xb[ci];                        // row0: float4 col ci
            xv[1] = xb[256 + ci];                  // row1
            #pragma unroll
            for (int e = 0; e < E; e++) {
                const float4 wv = ws[e * (H / 4) + ci];
                #pragma unroll
                for (int r = 0; r < RPW; r++) {
                    acc[r][e] += xv[r].x * wv.x;
                    acc[r][e] += xv[r].y * wv.y;
                    acc[r][e] += xv[r].z * wv.z;
                    acc[r][e] += xv[r].w * wv.w;
                }
            }
        }

        // Warp butterfly reduce (identical to R5).
        #pragma unroll
        for (int off = 16; off > 0; off >>= 1)
            #pragma unroll
            for (int r = 0; r < RPW; r++)
                #pragma unroll
                for (int e = 0; e < E; e++)
                    acc[r][e] += __shfl_xor_sync(0xffffffffu, acc[r][e], off);

        // Lanes 0..1 finish one row each (identical epilogue).
        int row0 = (blockIdx.x + g * GRID) * GROUP_ROWS + wid * RPW;
        if (row0 > n - RPW) row0 = n - RPW;
        if (lane < RPW && (row0 + lane) < n) {
            float l[E];
            #pragma unroll
            for (int r = 0; r < RPW; r++)
                if (lane == r) {
                    #pragma unroll
                    for (int e = 0; e < E; e++) l[e] = acc[r][e];
                }

            const float m = fmaxf(fmaxf(l[0], l[1]), fmaxf(l[2], l[3]));
            float p2[E];
            float s = 0.0f;
            #pragma unroll
            for (int e = 0; e < E; e++) {
                const float aa = l[e] - m;
                p2[e] = (aa <= EXP_FLUSH_T) ? 0.0f : expf(aa);
                s += p2[e];
            }
            int i1 = 0; float b1 = p2[0];
            #pragma unroll
            for (int e = 1; e < E; e++)
                if (p2[e] > b1) { b1 = p2[e]; i1 = e; }
            int i2 = -1; float b2 = -1.0f;
            #pragma unroll
            for (int e = 0; e < E; e++)
                if (e != i1 && p2[e] > b2) { b2 = p2[e]; i2 = e; }

            const float inv = 1.0f / s;
            const int row = row0 + lane;
            reinterpret_cast<float2*>(out)[row] =
                make_float2((float)i1, (float)i2);
            reinterpret_cast<float2*>(out + 2 * (size_t)n)[row] =
                make_float2(b1 * inv, b2 * inv);
        }
    }
}

extern "C" void kernel_launch(void* const* d_in, const int* in_sizes, int n_in,
                              void* d_out, int out_size)
{
    const float* x = (const float*)d_in[0];
    const float* w = (const float*)d_in[1];
    float* out = (float*)d_out;

    const int h = in_sizes[1] / E;                         // 1024
    const int n = in_sizes[0] / h;                         // 32768 rows
    const int ngroups = (n + GROUP_ROWS - 1) / GROUP_ROWS; // 2048
    (void)n_in; (void)out_size;

    static bool attr_done = false;
    if (!attr_done) {
        cudaFuncSetAttribute(moe_gate_kernel,
                             cudaFuncAttributeMaxDynamicSharedMemorySize,
                             SMEM_BYTES);
        attr_done = true;
    }

    moe_gate_kernel<<<GRID, THREADS, SMEM_BYTES>>>(x, w, out, n, ngroups);
}

// round 16
// speedup vs baseline: 1.1262x; 1.0755x over previous
#include <cuda_runtime.h>
#include <cuda_bf16.h>
#include <cstdint>

// MoE gate: logits = x[N,1024] @ W[4,1024]^T in exact fp32, softmax with
// FTZ-exp emulation, top-2 with lowest-index tie-break on flushed (zero)
// scores. Output (fp32): [ topk_idx (N*2) | topk_weight (N*2) | aux_loss(1) ]
// aux_loss == 0.01 analytically.
//
// R16: R15 (contiguous warp-autonomous cp.async tiles) + WEIGHTS IN
// REGISTERS. R15's binder was the smem crossbar: 4:1 smem:DRAM traffic
// (tile STS + x LDS + 16KB weight LDS per 8KB tile) = ~140 B/cyc at the
// 128 B/cyc cap. Each lane's weight columns (c*32+lane) are fixed, so
// wreg[4][8] (128 regs) removes the weight LDS entirely -> 2:1 ratio.
// Accumulation order bit-identical to R5/R15 (canary 1.032705e-06).

constexpr int H        = 1024;
constexpr int E        = 4;
constexpr int THREADS  = 256;
constexpr int WARPS    = THREADS / 32;     // 8
constexpr int RPW      = 2;                // rows per warp-tile
constexpr int GROUP_ROWS = WARPS * RPW;    // 16 rows per block-iteration
constexpr int SLOTS    = 3;                // per-warp ring depth
constexpr int TILE_F4  = RPW * (H / 4);    // 512 float4 = 8KB
constexpr int SMEM_BYTES = (WARPS * SLOTS * TILE_F4) * 16;  // 192KB
constexpr int GRID     = 148;              // 1 block/SM, persistent

#define EXP_FLUSH_T (-87.336544f)

__device__ __forceinline__ uint32_t s2u(const void* p) {
    return (uint32_t)__cvta_generic_to_shared(p);
}

__global__ __launch_bounds__(THREADS, 1)
void moe_gate_kernel(const float* __restrict__ x,
                     const float* __restrict__ w,
                     float* __restrict__ out, int n, int ngroups)
{
    extern __shared__ float4 smem[];
    float4* xs = smem;                       // 8 x 3 x 8KB warp rings

    const int tid  = threadIdx.x;
    const int lane = tid & 31;
    const int wid  = tid >> 5;

    const int my_ngroups = (blockIdx.x < ngroups)
                         ? ((ngroups - 1 - blockIdx.x) / GRID + 1) : 0;

    float4* ring = xs + wid * SLOTS * TILE_F4;

    // Issue this warp's tile for group-index g: 2 contiguous rows (8KB).
    // Unconditional commit keeps wait_group counting uniform at the tail.
    auto issue = [&](int g) {
        if (g < my_ngroups) {
            int row0 = (blockIdx.x + g * GRID) * GROUP_ROWS + wid * RPW;
            if (row0 > n - RPW) row0 = n - RPW;     // safety clamp
            const float4* src =
                reinterpret_cast<const float4*>(x) + (size_t)row0 * (H / 4);
            float4* dst = ring + (g % SLOTS) * TILE_F4;
            #pragma unroll
            for (int i = 0; i < TILE_F4 / 32; i++) {   // 16 per lane
                const int idx = i * 32 + lane;          // 512B coalesced/instr
                asm volatile("cp.async.cg.shared.global [%0], [%1], 16;"
                             :: "r"(s2u(dst + idx)), "l"(src + idx));
            }
        }
        asm volatile("cp.async.commit_group;");
    };

    issue(0);
    issue(1);

    // Per-lane weight registers: lane's float4-columns are c*32+lane,
    // c = 0..7, for each of the 4 experts. 32 float4 = 128 regs.
    // For fixed (e,c) lanes read consecutive float4s -> coalesced.
    float4 wreg[E][8];
    #pragma unroll
    for (int e = 0; e < E; e++)
        #pragma unroll
        for (int c = 0; c < 8; c++)
            wreg[e][c] = reinterpret_cast<const float4*>(w)
                             [e * (H / 4) + c * 32 + lane];

    if (blockIdx.x == 0 && tid == 0)
        out[4 * (size_t)n] = 0.01f;    // aux = 0.25*4*0.01 (analytic)

    for (int g = 0; g < my_ngroups; g++) {
        issue(g + 2);                              // into freed slot (g-1)%3
        asm volatile("cp.async.wait_group 2;" ::: "memory");  // tile g ready

        const float4* xb = ring + (g % SLOTS) * TILE_F4;

        float acc[RPW][E];
        #pragma unroll
        for (int r = 0; r < RPW; r++)
            #pragma unroll
            for (int e = 0; e < E; e++) acc[r][e] = 0.0f;

        #pragma unroll
        for (int c = 0; c < 8; c++) {              // 8 chunks, same as R5
            const int ci = c * 32 + lane;
            float4 xv[RPW];
            xv[0] = xb[ci];                        // row0: float4 col ci
            xv[1] = xb[256 + ci];                  // row1
            #pragma unroll
            for (int e = 0; e < E; e++) {
                const float4 wv = wreg[e][c];
                #pragma unroll
                for (int r = 0; r < RPW; r++) {
                    acc[r][e] += xv[r].x * wv.x;
                    acc[r][e] += xv[r].y * wv.y;
                    acc[r][e] += xv[r].z * wv.z;
                    acc[r][e] += xv[r].w * wv.w;
                }
            }
        }

        // Warp butterfly reduce (identical to R5).
        #pragma unroll
        for (int off = 16; off > 0; off >>= 1)
            #pragma unroll
            for (int r = 0; r < RPW; r++)
                #pragma unroll
                for (int e = 0; e < E; e++)
                    acc[r][e] += __shfl_xor_sync(0xffffffffu, acc[r][e], off);

        // Lanes 0..1 finish one row each (identical epilogue).
        int row0 = (blockIdx.x + g * GRID) * GROUP_ROWS + wid * RPW;
        if (row0 > n - RPW) row0 = n - RPW;
        if (lane < RPW && (row0 + lane) < n) {
            float l[E];
            #pragma unroll
            for (int r = 0; r < RPW; r++)
                if (lane == r) {
                    #pragma unroll
                    for (int e = 0; e < E; e++) l[e] = acc[r][e];
                }

            const float m = fmaxf(fmaxf(l[0], l[1]), fmaxf(l[2], l[3]));
            float p2[E];
            float s = 0.0f;
            #pragma unroll
            for (int e = 0; e < E; e++) {
                const float aa = l[e] - m;
                p2[e] = (aa <= EXP_FLUSH_T) ? 0.0f : expf(aa);
                s += p2[e];
            }
            int i1 = 0; float b1 = p2[0];
            #pragma unroll
            for (int e = 1; e < E; e++)
                if (p2[e] > b1) { b1 = p2[e]; i1 = e; }
            int i2 = -1; float b2 = -1.0f;
            #pragma unroll
            for (int e = 0; e < E; e++)
                if (e != i1 && p2[e] > b2) { b2 = p2[e]; i2 = e; }

            const float inv = 1.0f / s;
            const int row = row0 + lane;
            reinterpret_cast<float2*>(out)[row] =
                make_float2((float)i1, (float)i2);
            reinterpret_cast<float2*>(out + 2 * (size_t)n)[row] =
                make_float2(b1 * inv, b2 * inv);
        }
    }
}

extern "C" void kernel_launch(void* const* d_in, const int* in_sizes, int n_in,
                              void* d_out, int out_size)
{
    const float* x = (const float*)d_in[0];
    const float* w = (const float*)d_in[1];
    float* out = (float*)d_out;

    const int h = in_sizes[1] / E;                         // 1024
    const int n = in_sizes[0] / h;                         // 32768 rows
    const int ngroups = (n + GROUP_ROWS - 1) / GROUP_ROWS; // 2048
    (void)n_in; (void)out_size;

    static bool attr_done = false;
    if (!attr_done) {
        cudaFuncSetAttribute(moe_gate_kernel,
                             cudaFuncAttributeMaxDynamicSharedMemorySize,
                             SMEM_BYTES);
        attr_done = true;
    }

    moe_gate_kernel<<<GRID, THREADS, SMEM_BYTES>>>(x, w, out, n, ngroups);
}